// round 8
// baseline (speedup 1.0000x reference)
#include <cuda_runtime.h>
#include <cstdint>

#define NB 8
#define NA 49104
#define NM 50
#define NK 80
#define NK4 (NK / 4)
#define TPB 256
#define NSTR 192                     // streaming threads (warps 0-5)
#define BPI ((NA + TPB - 1) / TPB)   // 192 blocks per image
#define NBLK (BPI * NB)
#define S4PITCH 21                   // padded row pitch for conflict-free combine

__device__ float    g_cls[NB];
__device__ float    g_reg[NB];
__device__ int      g_pos[NB];
__device__ unsigned g_ticket;

__device__ __forceinline__ float smooth_l1(float d) {
    d = fabsf(d);
    const float BETA = 1.0f / 9.0f;
    return (d <= BETA) ? (4.5f * d * d) : (d - 0.5f * BETA);
}

__device__ __forceinline__ float focal_neg4(float4 q) {
    float s;
    s  = q.x * q.x * __log2f(1.f - q.x);
    s += q.y * q.y * __log2f(1.f - q.y);
    s += q.z * q.z * __log2f(1.f - q.z);
    s += q.w * q.w * __log2f(1.f - q.w);
    return s;
}

__global__ __launch_bounds__(TPB, 6)
void retina_fused_kernel(const float* __restrict__ logits,
                         const float* __restrict__ regp,
                         const float* __restrict__ anchors,
                         const float* __restrict__ boxes,
                         const int*   __restrict__ classes,
                         float* __restrict__ out)
{
    __shared__ float4 sbox[NM];
    __shared__ float  sarea[NM];
    __shared__ int    scls[NM];
    __shared__ float  sw[TPB];             // per-anchor focal weight (0 or -0.75*ln2)
    __shared__ float  S4[TPB * S4PITCH];   // per-float4 focal sums, padded rows
    __shared__ float  sredf[8];
    __shared__ float  sredr[8];
    __shared__ int    sredi[8];
    __shared__ int    slast;

    const int b   = blockIdx.y;
    const int a0  = blockIdx.x * TPB;
    const int tid = threadIdx.x;
    const int na  = min(TPB, NA - a0);
    const int nf4 = na * NK4;

    if (tid < NM) {
        float4 bxv = ((const float4*)boxes)[b * NM + tid];
        sbox[tid]  = bxv;
        sarea[tid] = (bxv.z - bxv.x) * (bxv.w - bxv.y);
        scls[tid]  = classes[b * NM + tid];
    }
    __syncthreads();

    float reg_partial = 0.f;
    float cls_partial = 0.f;
    int   pos_partial = 0;
    const float C_NEG = -0.75f * 0.69314718055994531f;  // -0.75*ln2

    if (tid < NSTR) {
        // ---------- streaming warps: weight-independent focal sums ----------
        const float4* lg4 = (const float4*)(logits + ((size_t)b * NA + a0) * NK);
        int i = tid;
        #pragma unroll 1
        for (; i + 3 * NSTR < nf4; i += 4 * NSTR) {
            int i1 = i + NSTR, i2 = i + 2 * NSTR, i3 = i + 3 * NSTR;
            float4 q0 = __ldcs(&lg4[i]);
            float4 q1 = __ldcs(&lg4[i1]);
            float4 q2 = __ldcs(&lg4[i2]);
            float4 q3 = __ldcs(&lg4[i3]);
            S4[i  + i  / NK4] = focal_neg4(q0);   // idx = row*21 + col = i + i/20
            S4[i1 + i1 / NK4] = focal_neg4(q1);
            S4[i2 + i2 / NK4] = focal_neg4(q2);
            S4[i3 + i3 / NK4] = focal_neg4(q3);
        }
        for (; i < nf4; i += NSTR) {
            float4 q = __ldcs(&lg4[i]);
            S4[i + i / NK4] = focal_neg4(q);
        }
    } else {
        // ---------- IoU warps: 4 anchors per thread ----------
        const int j = tid - NSTR;              // 0..63
        #pragma unroll 1
        for (int k = 0; k < 4; k++) {
            const int aa = 4 * j + k;
            if (aa >= na) break;
            const int a = a0 + aa;
            float4 an = ((const float4*)anchors)[a];
            float areaA = (an.z - an.x) * (an.w - an.y);
            float bI = -1e30f, bU = 1.f;       // best iou = bI/bU
            int   bi = 0;
            #pragma unroll 10
            for (int jj = 0; jj < NM; jj++) {
                float4 bv = sbox[jj];
                float iw = fmaxf(fminf(an.z, bv.z) - fmaxf(an.x, bv.x), 0.f);
                float ih = fmaxf(fminf(an.w, bv.w) - fmaxf(an.y, bv.y), 0.f);
                float inter = iw * ih;
                float ua = fmaxf(areaA + sarea[jj] - inter, 1e-8f);
                if (bv.x == -1.0f) inter = -ua;   // padded -> iou = -1
                if (inter * bU > bI * ua) { bI = inter; bU = ua; bi = jj; }
            }
            bool pos = bI >= 0.5f * bU;
            bool neg = bI <  0.4f * bU;
            sw[aa] = (pos | neg) ? C_NEG : 0.f;

            if (pos) {
                pos_partial += 1;
                int tc = scls[bi] - 1;
                float p = logits[((size_t)b * NA + a) * NK + tc];
                float om = 1.f - p;
                cls_partial += 0.25f * om * om * (-__logf(p))
                             - 0.75f * p * p * (-__logf(om));
                float4 gb = sbox[bi];
                float aw = an.z - an.x, ah = an.w - an.y;
                float acx = an.x + 0.5f * aw, acy = an.y + 0.5f * ah;
                float gw0 = gb.z - gb.x, gh0 = gb.w - gb.y;
                float gcx = gb.x + 0.5f * gw0, gcy = gb.y + 0.5f * gh0;
                float gw = fmaxf(gw0, 1.f), gh = fmaxf(gh0, 1.f);
                float t0 = ((gcx - acx) / aw) * 10.f;
                float t1 = ((gcy - acy) / ah) * 10.f;
                float t2 = __logf(gw / aw) * 5.f;
                float t3 = __logf(gh / ah) * 5.f;
                float4 rp = ((const float4*)regp)[(size_t)b * NA + a];
                reg_partial += smooth_l1(t0 - rp.x) + smooth_l1(t1 - rp.y)
                             + smooth_l1(t2 - rp.z) + smooth_l1(t3 - rp.w);
            }
        }
    }
    __syncthreads();

    // ---------- combine: cls += sw[anchor] * sum(S4 row) ----------
    if (tid < na) {
        float wgt = sw[tid];
        if (wgt != 0.f) {
            const float* row = &S4[tid * S4PITCH];
            float s = 0.f;
            #pragma unroll
            for (int k = 0; k < NK4; k++) s += row[k];
            cls_partial = fmaf(wgt, s, cls_partial);
        }
    }

    // ---------- reduction ----------
    float cv = cls_partial, rv = reg_partial;
    int   pv = pos_partial;
    #pragma unroll
    for (int off = 16; off > 0; off >>= 1) {
        cv += __shfl_down_sync(0xffffffffu, cv, off);
        rv += __shfl_down_sync(0xffffffffu, rv, off);
        pv += __shfl_down_sync(0xffffffffu, pv, off);
    }
    int wid = tid >> 5, lid = tid & 31;
    if (lid == 0) { sredf[wid] = cv; sredr[wid] = rv; sredi[wid] = pv; }
    __syncthreads();
    if (wid == 0) {
        cv = (lid < 8) ? sredf[lid] : 0.f;
        rv = (lid < 8) ? sredr[lid] : 0.f;
        pv = (lid < 8) ? sredi[lid] : 0;
        #pragma unroll
        for (int off = 4; off > 0; off >>= 1) {
            cv += __shfl_down_sync(0xffffffffu, cv, off);
            rv += __shfl_down_sync(0xffffffffu, rv, off);
            pv += __shfl_down_sync(0xffffffffu, pv, off);
        }
        if (lid == 0) {
            atomicAdd(&g_cls[b], cv);
            atomicAdd(&g_reg[b], rv);
            atomicAdd(&g_pos[b], pv);
        }
    }

    // ---------- last-block finalize + self-reset ----------
    __threadfence();
    if (tid == 0) {
        unsigned t = atomicAdd(&g_ticket, 1u);
        slast = (t == (unsigned)(NBLK - 1));
    }
    __syncthreads();
    if (slast && tid == 0) {
        __threadfence();
        volatile float* vc = g_cls;
        volatile float* vr = g_reg;
        volatile int*   vp = g_pos;
        float cm = 0.f, rm = 0.f;
        #pragma unroll
        for (int i2 = 0; i2 < NB; i2++) {
            float d = fmaxf((float)vp[i2], 1.f);
            cm += vc[i2] / d;
            rm += vr[i2] / (4.f * d);
        }
        cm /= (float)NB;
        rm /= (float)NB;
        out[0] = cm;
        out[1] = rm;
        out[2] = cm + rm;
        #pragma unroll
        for (int i2 = 0; i2 < NB; i2++) { g_cls[i2] = 0.f; g_reg[i2] = 0.f; g_pos[i2] = 0; }
        g_ticket = 0u;
    }
}

extern "C" void kernel_launch(void* const* d_in, const int* in_sizes, int n_in,
                              void* d_out, int out_size)
{
    const float* logits  = (const float*)d_in[0];   // (B,A,K)
    const float* regp    = (const float*)d_in[1];   // (B,A,4)
    const float* anchors = (const float*)d_in[2];   // (A,4)
    const float* boxes   = (const float*)d_in[3];   // (B,M,4)
    const int*   classes = (const int*)  d_in[4];   // (B,M)
    float* out = (float*)d_out;

    dim3 grid(BPI, NB);
    retina_fused_kernel<<<grid, TPB>>>(logits, regp, anchors, boxes, classes, out);
}

// round 9
// speedup vs baseline: 1.0525x; 1.0525x over previous
#include <cuda_runtime.h>
#include <cstdint>

#define NB 8
#define NA 49104
#define NM 50
#define NK 80
#define NK4 (NK / 4)
#define TPB 256
#define BPI ((NA + TPB - 1) / TPB)   // 192 blocks per image
#define NBLK (BPI * NB)
#define S4PITCH 21                   // padded row pitch, gcd(21,32)=1 -> conflict-free

__device__ float    g_cls[NB];
__device__ float    g_reg[NB];
__device__ int      g_pos[NB];
__device__ unsigned g_ticket;

__device__ __forceinline__ float smooth_l1(float d) {
    d = fabsf(d);
    const float BETA = 1.0f / 9.0f;
    return (d <= BETA) ? (4.5f * d * d) : (d - 0.5f * BETA);
}

__device__ __forceinline__ float focal_neg4(float4 q) {
    float s;
    s  = q.x * q.x * __log2f(1.f - q.x);
    s += q.y * q.y * __log2f(1.f - q.y);
    s += q.z * q.z * __log2f(1.f - q.z);
    s += q.w * q.w * __log2f(1.f - q.w);
    return s;
}

// IoU argmax + weight + positive-anchor losses for anchor index a (global).
// Returns focal weight (0 or -0.75*ln2); accumulates reg/cls/pos for positives.
__device__ __forceinline__ float anchor_assign(
    int a, int b,
    const float4* __restrict__ sbox, const float* __restrict__ sarea,
    const int* __restrict__ scls,
    const float* __restrict__ logits, const float* __restrict__ regp,
    const float* __restrict__ anchors,
    float& cls_partial, float& reg_partial, int& pos_partial)
{
    const float C_NEG = -0.75f * 0.69314718055994531f;  // -0.75*ln2
    float4 an = ((const float4*)anchors)[a];
    float areaA = (an.z - an.x) * (an.w - an.y);
    float bI = -1e30f, bU = 1.f;   // best iou = bI/bU
    int   bi = 0;
    #pragma unroll 10
    for (int j = 0; j < NM; j++) {
        float4 bv = sbox[j];
        float iw = fmaxf(fminf(an.z, bv.z) - fmaxf(an.x, bv.x), 0.f);
        float ih = fmaxf(fminf(an.w, bv.w) - fmaxf(an.y, bv.y), 0.f);
        float inter = iw * ih;
        float ua = fmaxf(areaA + sarea[j] - inter, 1e-8f);
        if (bv.x == -1.0f) inter = -ua;          // padded -> iou = -1
        if (inter * bU > bI * ua) { bI = inter; bU = ua; bi = j; }
    }
    bool pos = bI >= 0.5f * bU;
    bool neg = bI <  0.4f * bU;

    if (pos) {
        pos_partial += 1;
        int tc = scls[bi] - 1;
        float p = logits[((size_t)b * NA + a) * NK + tc];
        float om = 1.f - p;
        cls_partial += 0.25f * om * om * (-__logf(p))
                     - 0.75f * p * p * (-__logf(om));
        float4 gb = sbox[bi];
        float aw = an.z - an.x, ah = an.w - an.y;
        float acx = an.x + 0.5f * aw, acy = an.y + 0.5f * ah;
        float gw0 = gb.z - gb.x, gh0 = gb.w - gb.y;
        float gcx = gb.x + 0.5f * gw0, gcy = gb.y + 0.5f * gh0;
        float gw = fmaxf(gw0, 1.f), gh = fmaxf(gh0, 1.f);
        float t0 = ((gcx - acx) / aw) * 10.f;
        float t1 = ((gcy - acy) / ah) * 10.f;
        float t2 = __logf(gw / aw) * 5.f;
        float t3 = __logf(gh / ah) * 5.f;
        float4 rp = ((const float4*)regp)[(size_t)b * NA + a];
        reg_partial += smooth_l1(t0 - rp.x) + smooth_l1(t1 - rp.y)
                     + smooth_l1(t2 - rp.z) + smooth_l1(t3 - rp.w);
    }
    return (pos | neg) ? C_NEG : 0.f;
}

__global__ __launch_bounds__(TPB, 6)
void retina_fused_kernel(const float* __restrict__ logits,
                         const float* __restrict__ regp,
                         const float* __restrict__ anchors,
                         const float* __restrict__ boxes,
                         const int*   __restrict__ classes,
                         float* __restrict__ out)
{
    __shared__ float4 sbox[NM];
    __shared__ float  sarea[NM];
    __shared__ int    scls[NM];
    __shared__ float  sw[TPB];             // per-anchor focal weight
    __shared__ float  S4[TPB * S4PITCH];   // per-float4 focal sums (stream-first path)
    __shared__ float  sredf[8];
    __shared__ float  sredr[8];
    __shared__ int    sredi[8];
    __shared__ int    slast;

    const int b   = blockIdx.y;
    const int bx  = blockIdx.x;
    const int a0  = bx * TPB;
    const int tid = threadIdx.x;
    const int na  = min(TPB, NA - a0);
    const int nf4 = na * NK4;
    const float4* lg4 = (const float4*)(logits + ((size_t)b * NA + a0) * NK);

    if (tid < NM) {
        float4 bxv = ((const float4*)boxes)[b * NM + tid];
        sbox[tid]  = bxv;
        sarea[tid] = (bxv.z - bxv.x) * (bxv.w - bxv.y);
        scls[tid]  = classes[b * NM + tid];
    }
    __syncthreads();

    float reg_partial = 0.f;
    float cls_partial = 0.f;
    int   pos_partial = 0;

    if (bx & 1) {
        // ========== stream-first path ==========
        int i = tid;
        #pragma unroll 1
        for (; i + 3 * TPB < nf4; i += 4 * TPB) {
            int i1 = i + TPB, i2 = i + 2 * TPB, i3 = i + 3 * TPB;
            float4 q0 = __ldcs(&lg4[i]);
            float4 q1 = __ldcs(&lg4[i1]);
            float4 q2 = __ldcs(&lg4[i2]);
            float4 q3 = __ldcs(&lg4[i3]);
            S4[i  + i  / NK4] = focal_neg4(q0);
            S4[i1 + i1 / NK4] = focal_neg4(q1);
            S4[i2 + i2 / NK4] = focal_neg4(q2);
            S4[i3 + i3 / NK4] = focal_neg4(q3);
        }
        for (; i < nf4; i += TPB) {
            float4 q = __ldcs(&lg4[i]);
            S4[i + i / NK4] = focal_neg4(q);
        }
        // IoU (no barrier needed before: S4 rows read only by own writer-group
        // pattern after the barrier below)
        float wgt = 0.f;
        if (tid < na)
            wgt = anchor_assign(a0 + tid, b, sbox, sarea, scls,
                                logits, regp, anchors,
                                cls_partial, reg_partial, pos_partial);
        __syncthreads();
        if (tid < na && wgt != 0.f) {
            const float* row = &S4[tid * S4PITCH];
            float s = 0.f;
            #pragma unroll
            for (int k = 0; k < NK4; k++) s += row[k];
            cls_partial = fmaf(wgt, s, cls_partial);
        }
    } else {
        // ========== IoU-first path (R7 champion) ==========
        float wgt = 0.f;
        if (tid < na)
            wgt = anchor_assign(a0 + tid, b, sbox, sarea, scls,
                                logits, regp, anchors,
                                cls_partial, reg_partial, pos_partial);
        sw[tid] = wgt;
        __syncthreads();

        int i = tid;
        #pragma unroll 1
        for (; i + 3 * TPB < nf4; i += 4 * TPB) {
            int i1 = i + TPB, i2 = i + 2 * TPB, i3 = i + 3 * TPB;
            float4 q0 = __ldcs(&lg4[i]);
            float4 q1 = __ldcs(&lg4[i1]);
            float4 q2 = __ldcs(&lg4[i2]);
            float4 q3 = __ldcs(&lg4[i3]);
            cls_partial = fmaf(sw[i  / NK4], focal_neg4(q0), cls_partial);
            cls_partial = fmaf(sw[i1 / NK4], focal_neg4(q1), cls_partial);
            cls_partial = fmaf(sw[i2 / NK4], focal_neg4(q2), cls_partial);
            cls_partial = fmaf(sw[i3 / NK4], focal_neg4(q3), cls_partial);
        }
        for (; i < nf4; i += TPB) {
            float4 q = __ldcs(&lg4[i]);
            cls_partial = fmaf(sw[i / NK4], focal_neg4(q), cls_partial);
        }
    }

    // ---------- reduction ----------
    float cv = cls_partial, rv = reg_partial;
    int   pv = pos_partial;
    #pragma unroll
    for (int off = 16; off > 0; off >>= 1) {
        cv += __shfl_down_sync(0xffffffffu, cv, off);
        rv += __shfl_down_sync(0xffffffffu, rv, off);
        pv += __shfl_down_sync(0xffffffffu, pv, off);
    }
    int wid = tid >> 5, lid = tid & 31;
    if (lid == 0) { sredf[wid] = cv; sredr[wid] = rv; sredi[wid] = pv; }
    __syncthreads();
    if (wid == 0) {
        cv = (lid < 8) ? sredf[lid] : 0.f;
        rv = (lid < 8) ? sredr[lid] : 0.f;
        pv = (lid < 8) ? sredi[lid] : 0;
        #pragma unroll
        for (int off = 4; off > 0; off >>= 1) {
            cv += __shfl_down_sync(0xffffffffu, cv, off);
            rv += __shfl_down_sync(0xffffffffu, rv, off);
            pv += __shfl_down_sync(0xffffffffu, pv, off);
        }
        if (lid == 0) {
            atomicAdd(&g_cls[b], cv);
            atomicAdd(&g_reg[b], rv);
            atomicAdd(&g_pos[b], pv);
        }
    }

    // ---------- last-block finalize + self-reset ----------
    __threadfence();
    if (tid == 0) {
        unsigned t = atomicAdd(&g_ticket, 1u);
        slast = (t == (unsigned)(NBLK - 1));
    }
    __syncthreads();
    if (slast && tid == 0) {
        __threadfence();
        volatile float* vc = g_cls;
        volatile float* vr = g_reg;
        volatile int*   vp = g_pos;
        float cm = 0.f, rm = 0.f;
        #pragma unroll
        for (int i2 = 0; i2 < NB; i2++) {
            float d = fmaxf((float)vp[i2], 1.f);
            cm += vc[i2] / d;
            rm += vr[i2] / (4.f * d);
        }
        cm /= (float)NB;
        rm /= (float)NB;
        out[0] = cm;
        out[1] = rm;
        out[2] = cm + rm;
        #pragma unroll
        for (int i2 = 0; i2 < NB; i2++) { g_cls[i2] = 0.f; g_reg[i2] = 0.f; g_pos[i2] = 0; }
        g_ticket = 0u;
    }
}

extern "C" void kernel_launch(void* const* d_in, const int* in_sizes, int n_in,
                              void* d_out, int out_size)
{
    const float* logits  = (const float*)d_in[0];   // (B,A,K)
    const float* regp    = (const float*)d_in[1];   // (B,A,4)
    const float* anchors = (const float*)d_in[2];   // (A,4)
    const float* boxes   = (const float*)d_in[3];   // (B,M,4)
    const int*   classes = (const int*)  d_in[4];   // (B,M)
    float* out = (float*)d_out;

    dim3 grid(BPI, NB);
    retina_fused_kernel<<<grid, TPB>>>(logits, regp, anchors, boxes, classes, out);
}

// round 10
// speedup vs baseline: 1.1009x; 1.0460x over previous
#include <cuda_runtime.h>
#include <cstdint>

#define NB 8
#define NA 49104
#define NM 50
#define NK 80
#define NK4 (NK / 4)
#define TPB 256
#define BPI ((NA + TPB - 1) / TPB)   // 192 blocks per image
#define NBLK (BPI * NB)
#define S4PITCH 21                   // padded row pitch, conflict-free combine
#define NSM 148

__device__ float    g_cls[NB];
__device__ float    g_reg[NB];
__device__ int      g_pos[NB];
__device__ unsigned g_ticket;

__device__ __forceinline__ float smooth_l1(float d) {
    d = fabsf(d);
    const float BETA = 1.0f / 9.0f;
    return (d <= BETA) ? (4.5f * d * d) : (d - 0.5f * BETA);
}

__device__ __forceinline__ float focal_neg4(float4 q) {
    float s;
    s  = q.x * q.x * __log2f(1.f - q.x);
    s += q.y * q.y * __log2f(1.f - q.y);
    s += q.z * q.z * __log2f(1.f - q.z);
    s += q.w * q.w * __log2f(1.f - q.w);
    return s;
}

// Classify anchor (two-threshold max, no argmax); on positive, do argmax
// re-loop + losses. Returns focal weight (0 or -0.75*ln2).
__device__ __forceinline__ float anchor_assign(
    int a, int b,
    const float4* __restrict__ sbox, const float* __restrict__ sarea,
    const int* __restrict__ scls,
    const float* __restrict__ logits, const float* __restrict__ regp,
    const float* __restrict__ anchors,
    float& cls_partial, float& reg_partial, int& pos_partial)
{
    const float C_NEG = -0.75f * 0.69314718055994531f;  // -0.75*ln2
    float4 an = ((const float4*)anchors)[a];
    float areaA = (an.z - an.x) * (an.w - an.y);

    float m4 = -1e30f, m5 = -1e30f;
    #pragma unroll 10
    for (int j = 0; j < NM; j++) {
        float4 bv = sbox[j];
        float iw = fmaxf(fminf(an.z, bv.z) - fmaxf(an.x, bv.x), 0.f);
        float ih = fmaxf(fminf(an.w, bv.w) - fmaxf(an.y, bv.y), 0.f);
        float inter = iw * ih;
        float ua = areaA + sarea[j] - inter;       // >= 256 for valid, 1e18 padded
        m4 = fmaxf(m4, fmaf(-0.4f, ua, inter));
        m5 = fmaxf(m5, fmaf(-0.5f, ua, inter));
    }
    bool pos = m5 >= 0.f;
    bool neg = m4 <  0.f;

    if (pos) {
        // argmax re-loop (rare path)
        float bI = -1e30f, bU = 1.f;
        int   bi = 0;
        #pragma unroll 10
        for (int j = 0; j < NM; j++) {
            float4 bv = sbox[j];
            float iw = fmaxf(fminf(an.z, bv.z) - fmaxf(an.x, bv.x), 0.f);
            float ih = fmaxf(fminf(an.w, bv.w) - fmaxf(an.y, bv.y), 0.f);
            float inter = iw * ih;                 // padded box -> 0, never wins vs iou>=0.5
            float ua = areaA + sarea[j] - inter;
            if (inter * bU > bI * ua) { bI = inter; bU = ua; bi = j; }
        }
        pos_partial += 1;
        int tc = scls[bi] - 1;
        float p = logits[((size_t)b * NA + a) * NK + tc];
        float om = 1.f - p;
        cls_partial += 0.25f * om * om * (-__logf(p))
                     - 0.75f * p * p * (-__logf(om));
        float4 gb = sbox[bi];
        float aw = an.z - an.x, ah = an.w - an.y;
        float acx = an.x + 0.5f * aw, acy = an.y + 0.5f * ah;
        float gw0 = gb.z - gb.x, gh0 = gb.w - gb.y;
        float gcx = gb.x + 0.5f * gw0, gcy = gb.y + 0.5f * gh0;
        float gw = fmaxf(gw0, 1.f), gh = fmaxf(gh0, 1.f);
        float t0 = ((gcx - acx) / aw) * 10.f;
        float t1 = ((gcy - acy) / ah) * 10.f;
        float t2 = __logf(gw / aw) * 5.f;
        float t3 = __logf(gh / ah) * 5.f;
        float4 rp = ((const float4*)regp)[(size_t)b * NA + a];
        reg_partial += smooth_l1(t0 - rp.x) + smooth_l1(t1 - rp.y)
                     + smooth_l1(t2 - rp.z) + smooth_l1(t3 - rp.w);
    }
    return (pos | neg) ? C_NEG : 0.f;
}

__global__ __launch_bounds__(TPB, 6)
void retina_fused_kernel(const float* __restrict__ logits,
                         const float* __restrict__ regp,
                         const float* __restrict__ anchors,
                         const float* __restrict__ boxes,
                         const int*   __restrict__ classes,
                         float* __restrict__ out)
{
    __shared__ float4 sbox[NM];
    __shared__ float  sarea[NM];
    __shared__ int    scls[NM];
    __shared__ float  sw[TPB];             // per-anchor focal weight
    __shared__ float  S4[TPB * S4PITCH];   // per-float4 focal sums (stream-first path)
    __shared__ float  sredf[8];
    __shared__ float  sredr[8];
    __shared__ int    sredi[8];
    __shared__ int    slast;

    const int b   = blockIdx.y;
    const int bx  = blockIdx.x;
    const int lb  = b * BPI + bx;          // linear block id
    const int a0  = bx * TPB;
    const int tid = threadIdx.x;
    const int na  = min(TPB, NA - a0);
    const int nf4 = na * NK4;
    const float4* lg4 = (const float4*)(logits + ((size_t)b * NA + a0) * NK);

    if (tid < NM) {
        float4 bxv = ((const float4*)boxes)[b * NM + tid];
        bool padded = (bxv.x == -1.0f);
        sbox[tid]  = padded ? make_float4(0.f, 0.f, 0.f, 0.f) : bxv;
        sarea[tid] = padded ? 1e18f : (bxv.z - bxv.x) * (bxv.w - bxv.y);
        scls[tid]  = classes[b * NM + tid];
    }
    __syncthreads();

    float reg_partial = 0.f;
    float cls_partial = 0.f;
    int   pos_partial = 0;

    if ((lb / NSM) & 1) {
        // ========== stream-first path ==========
        int i = tid;
        #pragma unroll 1
        for (; i + 3 * TPB < nf4; i += 4 * TPB) {
            int i1 = i + TPB, i2 = i + 2 * TPB, i3 = i + 3 * TPB;
            float4 q0 = __ldcs(&lg4[i]);
            float4 q1 = __ldcs(&lg4[i1]);
            float4 q2 = __ldcs(&lg4[i2]);
            float4 q3 = __ldcs(&lg4[i3]);
            S4[i  + i  / NK4] = focal_neg4(q0);
            S4[i1 + i1 / NK4] = focal_neg4(q1);
            S4[i2 + i2 / NK4] = focal_neg4(q2);
            S4[i3 + i3 / NK4] = focal_neg4(q3);
        }
        for (; i < nf4; i += TPB) {
            float4 q = __ldcs(&lg4[i]);
            S4[i + i / NK4] = focal_neg4(q);
        }
        float wgt = 0.f;
        if (tid < na)
            wgt = anchor_assign(a0 + tid, b, sbox, sarea, scls,
                                logits, regp, anchors,
                                cls_partial, reg_partial, pos_partial);
        __syncthreads();
        if (tid < na && wgt != 0.f) {
            const float* row = &S4[tid * S4PITCH];
            float s = 0.f;
            #pragma unroll
            for (int k = 0; k < NK4; k++) s += row[k];
            cls_partial = fmaf(wgt, s, cls_partial);
        }
    } else {
        // ========== IoU-first path ==========
        float wgt = 0.f;
        if (tid < na)
            wgt = anchor_assign(a0 + tid, b, sbox, sarea, scls,
                                logits, regp, anchors,
                                cls_partial, reg_partial, pos_partial);
        sw[tid] = wgt;
        __syncthreads();

        int i = tid;
        #pragma unroll 1
        for (; i + 3 * TPB < nf4; i += 4 * TPB) {
            int i1 = i + TPB, i2 = i + 2 * TPB, i3 = i + 3 * TPB;
            float4 q0 = __ldcs(&lg4[i]);
            float4 q1 = __ldcs(&lg4[i1]);
            float4 q2 = __ldcs(&lg4[i2]);
            float4 q3 = __ldcs(&lg4[i3]);
            cls_partial = fmaf(sw[i  / NK4], focal_neg4(q0), cls_partial);
            cls_partial = fmaf(sw[i1 / NK4], focal_neg4(q1), cls_partial);
            cls_partial = fmaf(sw[i2 / NK4], focal_neg4(q2), cls_partial);
            cls_partial = fmaf(sw[i3 / NK4], focal_neg4(q3), cls_partial);
        }
        for (; i < nf4; i += TPB) {
            float4 q = __ldcs(&lg4[i]);
            cls_partial = fmaf(sw[i / NK4], focal_neg4(q), cls_partial);
        }
    }

    // ---------- reduction ----------
    float cv = cls_partial, rv = reg_partial;
    int   pv = pos_partial;
    #pragma unroll
    for (int off = 16; off > 0; off >>= 1) {
        cv += __shfl_down_sync(0xffffffffu, cv, off);
        rv += __shfl_down_sync(0xffffffffu, rv, off);
        pv += __shfl_down_sync(0xffffffffu, pv, off);
    }
    int wid = tid >> 5, lid = tid & 31;
    if (lid == 0) { sredf[wid] = cv; sredr[wid] = rv; sredi[wid] = pv; }
    __syncthreads();
    if (wid == 0) {
        cv = (lid < 8) ? sredf[lid] : 0.f;
        rv = (lid < 8) ? sredr[lid] : 0.f;
        pv = (lid < 8) ? sredi[lid] : 0;
        #pragma unroll
        for (int off = 4; off > 0; off >>= 1) {
            cv += __shfl_down_sync(0xffffffffu, cv, off);
            rv += __shfl_down_sync(0xffffffffu, rv, off);
            pv += __shfl_down_sync(0xffffffffu, pv, off);
        }
        if (lid == 0) {
            atomicAdd(&g_cls[b], cv);
            atomicAdd(&g_reg[b], rv);
            atomicAdd(&g_pos[b], pv);
        }
    }

    // ---------- last-block finalize + self-reset ----------
    __threadfence();
    if (tid == 0) {
        unsigned t = atomicAdd(&g_ticket, 1u);
        slast = (t == (unsigned)(NBLK - 1));
    }
    __syncthreads();
    if (slast && tid == 0) {
        __threadfence();
        volatile float* vc = g_cls;
        volatile float* vr = g_reg;
        volatile int*   vp = g_pos;
        float cm = 0.f, rm = 0.f;
        #pragma unroll
        for (int i2 = 0; i2 < NB; i2++) {
            float d = fmaxf((float)vp[i2], 1.f);
            cm += vc[i2] / d;
            rm += vr[i2] / (4.f * d);
        }
        cm /= (float)NB;
        rm /= (float)NB;
        out[0] = cm;
        out[1] = rm;
        out[2] = cm + rm;
        #pragma unroll
        for (int i2 = 0; i2 < NB; i2++) { g_cls[i2] = 0.f; g_reg[i2] = 0.f; g_pos[i2] = 0; }
        g_ticket = 0u;
    }
}

extern "C" void kernel_launch(void* const* d_in, const int* in_sizes, int n_in,
                              void* d_out, int out_size)
{
    const float* logits  = (const float*)d_in[0];   // (B,A,K)
    const float* regp    = (const float*)d_in[1];   // (B,A,4)
    const float* anchors = (const float*)d_in[2];   // (A,4)
    const float* boxes   = (const float*)d_in[3];   // (B,M,4)
    const int*   classes = (const int*)  d_in[4];   // (B,M)
    float* out = (float*)d_out;

    dim3 grid(BPI, NB);
    retina_fused_kernel<<<grid, TPB>>>(logits, regp, anchors, boxes, classes, out);
}

// round 12
// speedup vs baseline: 1.2277x; 1.1152x over previous
#include <cuda_runtime.h>
#include <cstdint>

#define NB 8
#define NA 49104
#define NM 50
#define NK 80
#define NK4 (NK / 4)
#define TPB 256
#define BPI ((NA + TPB - 1) / TPB)   // 192 blocks per image
#define NBLK (BPI * NB)
#define S4PITCH 21                   // padded row pitch, conflict-free combine
#define NCHUNK 5                     // 5 chunks x 4 loads = 20 float4/thread
#define LBOX 10                      // boxes per chunk

__device__ float    g_cls[NB];
__device__ float    g_reg[NB];
__device__ int      g_pos[NB];
__device__ unsigned g_ticket;

__device__ __forceinline__ float smooth_l1(float d) {
    d = fabsf(d);
    const float BETA = 1.0f / 9.0f;
    return (d <= BETA) ? (4.5f * d * d) : (d - 0.5f * BETA);
}

__device__ __forceinline__ float focal_neg4(float4 q) {
    float s;
    s  = q.x * q.x * __log2f(1.f - q.x);
    s += q.y * q.y * __log2f(1.f - q.y);
    s += q.z * q.z * __log2f(1.f - q.z);
    s += q.w * q.w * __log2f(1.f - q.w);
    return s;
}

__global__ __launch_bounds__(TPB, 5)
void retina_fused_kernel(const float* __restrict__ logits,
                         const float* __restrict__ regp,
                         const float* __restrict__ anchors,
                         const float* __restrict__ boxes,
                         const int*   __restrict__ classes,
                         float* __restrict__ out)
{
    __shared__ float4 sbox[NM];
    __shared__ float  sarea[NM];
    __shared__ int    scls[NM];
    __shared__ float  S4[TPB * S4PITCH];   // per-float4 weight-independent focal sums
    __shared__ float  sredf[8];
    __shared__ float  sredr[8];
    __shared__ int    sredi[8];
    __shared__ int    slast;

    const int b   = blockIdx.y;
    const int bx  = blockIdx.x;
    const int a0  = bx * TPB;
    const int tid = threadIdx.x;
    const int na  = min(TPB, NA - a0);
    const int nf4 = na * NK4;
    const float4* lg4 = (const float4*)(logits + ((size_t)b * NA + a0) * NK);

    bool bval = false;
    if (tid < NM) {
        float4 bxv = ((const float4*)boxes)[b * NM + tid];
        bval = (bxv.x != -1.0f);
        sbox[tid]  = bxv;
        sarea[tid] = (bxv.z - bxv.x) * (bxv.w - bxv.y);
        scls[tid]  = classes[b * NM + tid];
    }
    const int nv = __syncthreads_count(bval);   // valid boxes = contiguous prefix

    float reg_partial = 0.f;
    float cls_partial = 0.f;
    int   pos_partial = 0;
    const float C_NEG = -0.75f * 0.69314718055994531f;  // -0.75*ln2

    // per-anchor state
    float4 an = make_float4(0.f, 0.f, 0.f, 0.f);
    float areaA = 0.f;
    float m4 = -1e30f, m5 = -1e30f;
    if (tid < na) {
        an = ((const float4*)anchors)[a0 + tid];
        areaA = (an.z - an.x) * (an.w - an.y);
    }

    if (na == TPB) {
        // ===== fused pipeline: batched loads hide behind IoU math =====
        #pragma unroll 1
        for (int c = 0; c < NCHUNK; c++) {
            const int i0 = (c * 4) * TPB + tid;
            const int i1 = i0 + TPB, i2 = i0 + 2 * TPB, i3 = i0 + 3 * TPB;
            float4 q0 = __ldcs(&lg4[i0]);
            float4 q1 = __ldcs(&lg4[i1]);
            float4 q2 = __ldcs(&lg4[i2]);
            float4 q3 = __ldcs(&lg4[i3]);

            const int jend = min((c + 1) * LBOX, nv);
            #pragma unroll 2
            for (int j = c * LBOX; j < jend; j++) {
                float4 bv = sbox[j];
                float iw = fmaxf(fminf(an.z, bv.z) - fmaxf(an.x, bv.x), 0.f);
                float ih = fmaxf(fminf(an.w, bv.w) - fmaxf(an.y, bv.y), 0.f);
                float inter = iw * ih;
                float ua = areaA + sarea[j] - inter;
                m4 = fmaxf(m4, fmaf(-0.4f, ua, inter));
                m5 = fmaxf(m5, fmaf(-0.5f, ua, inter));
            }

            S4[i0 + i0 / NK4] = focal_neg4(q0);
            S4[i1 + i1 / NK4] = focal_neg4(q1);
            S4[i2 + i2 / NK4] = focal_neg4(q2);
            S4[i3 + i3 / NK4] = focal_neg4(q3);
        }
    } else {
        // ===== generic path (last ragged block only) =====
        for (int i = tid; i < nf4; i += TPB) {
            float4 q = __ldcs(&lg4[i]);
            S4[i + i / NK4] = focal_neg4(q);
        }
        if (tid < na) {
            #pragma unroll 2
            for (int j = 0; j < nv; j++) {
                float4 bv = sbox[j];
                float iw = fmaxf(fminf(an.z, bv.z) - fmaxf(an.x, bv.x), 0.f);
                float ih = fmaxf(fminf(an.w, bv.w) - fmaxf(an.y, bv.y), 0.f);
                float inter = iw * ih;
                float ua = areaA + sarea[j] - inter;
                m4 = fmaxf(m4, fmaf(-0.4f, ua, inter));
                m5 = fmaxf(m5, fmaf(-0.5f, ua, inter));
            }
        }
    }

    // ---------- classification + positive-anchor losses ----------
    float wgt = 0.f;
    if (tid < na) {
        bool pos = m5 >= 0.f;
        bool neg = m4 <  0.f;
        wgt = (pos | neg) ? C_NEG : 0.f;
        if (pos) {
            const int a = a0 + tid;
            float bI = -1e30f, bU = 1.f;
            int   bi = 0;
            #pragma unroll 2
            for (int j = 0; j < nv; j++) {
                float4 bv = sbox[j];
                float iw = fmaxf(fminf(an.z, bv.z) - fmaxf(an.x, bv.x), 0.f);
                float ih = fmaxf(fminf(an.w, bv.w) - fmaxf(an.y, bv.y), 0.f);
                float inter = iw * ih;
                float ua = areaA + sarea[j] - inter;
                if (inter * bU > bI * ua) { bI = inter; bU = ua; bi = j; }
            }
            pos_partial = 1;
            int tc = scls[bi] - 1;
            float p = logits[((size_t)b * NA + a) * NK + tc];
            float om = 1.f - p;
            cls_partial = 0.25f * om * om * (-__logf(p))
                        - 0.75f * p * p * (-__logf(om));
            float4 gb = sbox[bi];
            float aw = an.z - an.x, ah = an.w - an.y;
            float acx = an.x + 0.5f * aw, acy = an.y + 0.5f * ah;
            float gw0 = gb.z - gb.x, gh0 = gb.w - gb.y;
            float gcx = gb.x + 0.5f * gw0, gcy = gb.y + 0.5f * gh0;
            float gw = fmaxf(gw0, 1.f), gh = fmaxf(gh0, 1.f);
            float t0 = ((gcx - acx) / aw) * 10.f;
            float t1 = ((gcy - acy) / ah) * 10.f;
            float t2 = __logf(gw / aw) * 5.f;
            float t3 = __logf(gh / ah) * 5.f;
            float4 rp = ((const float4*)regp)[(size_t)b * NA + a];
            reg_partial = smooth_l1(t0 - rp.x) + smooth_l1(t1 - rp.y)
                        + smooth_l1(t2 - rp.z) + smooth_l1(t3 - rp.w);
        }
    }
    __syncthreads();   // S4 complete

    // ---------- combine: cls += wgt * sum(S4 row) ----------
    if (tid < na && wgt != 0.f) {
        const float* row = &S4[tid * S4PITCH];
        float s = 0.f;
        #pragma unroll
        for (int k = 0; k < NK4; k++) s += row[k];
        cls_partial = fmaf(wgt, s, cls_partial);
    }

    // ---------- reduction ----------
    float cv = cls_partial, rv = reg_partial;
    int   pv = pos_partial;
    #pragma unroll
    for (int off = 16; off > 0; off >>= 1) {
        cv += __shfl_down_sync(0xffffffffu, cv, off);
        rv += __shfl_down_sync(0xffffffffu, rv, off);
        pv += __shfl_down_sync(0xffffffffu, pv, off);
    }
    int wid = tid >> 5, lid = tid & 31;
    if (lid == 0) { sredf[wid] = cv; sredr[wid] = rv; sredi[wid] = pv; }
    __syncthreads();
    if (wid == 0) {
        cv = (lid < 8) ? sredf[lid] : 0.f;
        rv = (lid < 8) ? sredr[lid] : 0.f;
        pv = (lid < 8) ? sredi[lid] : 0;
        #pragma unroll
        for (int off = 4; off > 0; off >>= 1) {
            cv += __shfl_down_sync(0xffffffffu, cv, off);
            rv += __shfl_down_sync(0xffffffffu, rv, off);
            pv += __shfl_down_sync(0xffffffffu, pv, off);
        }
        if (lid == 0) {
            atomicAdd(&g_cls[b], cv);
            atomicAdd(&g_reg[b], rv);
            atomicAdd(&g_pos[b], pv);
        }
    }

    // ---------- last-block finalize + self-reset ----------
    __threadfence();
    if (tid == 0) {
        unsigned t = atomicAdd(&g_ticket, 1u);
        slast = (t == (unsigned)(NBLK - 1));
    }
    __syncthreads();
    if (slast && tid == 0) {
        __threadfence();
        volatile float* vc = g_cls;
        volatile float* vr = g_reg;
        volatile int*   vp = g_pos;
        float cm = 0.f, rm = 0.f;
        #pragma unroll
        for (int i2 = 0; i2 < NB; i2++) {
            float d = fmaxf((float)vp[i2], 1.f);
            cm += vc[i2] / d;
            rm += vr[i2] / (4.f * d);
        }
        cm /= (float)NB;
        rm /= (float)NB;
        out[0] = cm;
        out[1] = rm;
        out[2] = cm + rm;
        #pragma unroll
        for (int i2 = 0; i2 < NB; i2++) { g_cls[i2] = 0.f; g_reg[i2] = 0.f; g_pos[i2] = 0; }
        g_ticket = 0u;
    }
}

extern "C" void kernel_launch(void* const* d_in, const int* in_sizes, int n_in,
                              void* d_out, int out_size)
{
    const float* logits  = (const float*)d_in[0];   // (B,A,K)
    const float* regp    = (const float*)d_in[1];   // (B,A,4)
    const float* anchors = (const float*)d_in[2];   // (A,4)
    const float* boxes   = (const float*)d_in[3];   // (B,M,4)
    const int*   classes = (const int*)  d_in[4];   // (B,M)
    float* out = (float*)d_out;

    dim3 grid(BPI, NB);
    retina_fused_kernel<<<grid, TPB>>>(logits, regp, anchors, boxes, classes, out);
}